// round 15
// baseline (speedup 1.0000x reference)
#include <cuda_runtime.h>
#include <cuda_bf16.h>
#include <stdint.h>

typedef __nv_bfloat16 bf16;

#define BB 8
#define LQ 512
#define LC 2048
#define DD 768

// ---------------- scratch (device globals; allocation-free) ----------------
__device__ __align__(128) uint8_t g_C8[BB * LC * DD];   // e4m3 context
__device__ __align__(128) uint8_t g_Q8[BB * LQ * DD];   // e4m3 query
__device__ __align__(128) bf16    g_S[BB * LC * LQ];    // approximate logits

// ---------------- helpers ----------------
__device__ __forceinline__ uint32_t smem_u32(const void* p) {
    uint32_t a;
    asm("{ .reg .u64 t; cvta.to.shared.u64 t, %1; cvt.u32.u64 %0, t; }" : "=r"(a) : "l"(p));
    return a;
}
#define CP_ASYNC16(dst, src) \
    asm volatile("cp.async.cg.shared.global [%0], [%1], 16;" :: "r"(dst), "l"(src))
#define CP_COMMIT() asm volatile("cp.async.commit_group;" ::: "memory")
#define CP_WAIT2()  asm volatile("cp.async.wait_group 2;" ::: "memory")
#define CP_WAIT0()  asm volatile("cp.async.wait_group 0;" ::: "memory")

__device__ __forceinline__ void ldsm_x4(uint32_t* r, uint32_t a) {
    asm volatile("ldmatrix.sync.aligned.m8n8.x4.shared.b16 {%0,%1,%2,%3}, [%4];"
                 : "=r"(r[0]), "=r"(r[1]), "=r"(r[2]), "=r"(r[3]) : "r"(a));
}
// FP8 e4m3 MMA: m16n8k32, fp32 accumulate (sm_89+ baseline PTX).
__device__ __forceinline__ void mma_fp8(float* d, const uint32_t* a, const uint32_t* b) {
    asm volatile(
        "mma.sync.aligned.m16n8k32.row.col.f32.e4m3.e4m3.f32 "
        "{%0,%1,%2,%3}, {%4,%5,%6,%7}, {%8,%9}, {%0,%1,%2,%3};"
        : "+f"(d[0]), "+f"(d[1]), "+f"(d[2]), "+f"(d[3])
        : "r"(a[0]), "r"(a[1]), "r"(a[2]), "r"(a[3]), "r"(b[0]), "r"(b[1]));
}

// ---------------- kernel: fp32 -> e4m3 convert ----------------
__global__ __launch_bounds__(256)
void to_fp8_kernel(const float* __restrict__ x, uint32_t* __restrict__ out, int n4) {
    int i = blockIdx.x * 256 + threadIdx.x;
    if (i >= n4) return;
    float4 v = reinterpret_cast<const float4*>(x)[i];
    uint16_t lo, hi;
    // first f32 source -> upper byte; pass (later, earlier) to keep memory order
    asm("cvt.rn.satfinite.e4m3x2.f32 %0, %1, %2;" : "=h"(lo) : "f"(v.y), "f"(v.x));
    asm("cvt.rn.satfinite.e4m3x2.f32 %0, %1, %2;" : "=h"(hi) : "f"(v.w), "f"(v.z));
    out[i] = (uint32_t)lo | ((uint32_t)hi << 16);
}

// ---------------- FP8 screening GEMM ----------------
// S_approx[c][q] = sum_d C8[c,d]*Q8[q,d], fp32 acc, stored bf16.
// Chunk = 64 fp8 (64B/row, pitch 80 — byte-identical addressing to the proven
// bf16 kernel; k-step = 32 fp8 = 32B, 2 steps/chunk). nchunks = 12.
#define PITCH    80
#define STG_SIZE 20480
#define NSTG     4
#define SM_TOTAL (NSTG * STG_SIZE)   // 81920 -> 2 CTAs/SM

__global__ __launch_bounds__(256, 2)
void gemm_fp8(const uint8_t* __restrict__ A, int lda, long sAb,
              const uint8_t* __restrict__ B, int ldb, long sBb,
              int nchunks,
              bf16* __restrict__ D, int ldd, long sDb) {
    extern __shared__ char smem[];
    const uint32_t sbase = smem_u32(smem);
    const int tid = threadIdx.x, wid = tid >> 5, lane = tid & 31;
    const int b  = blockIdx.z;
    const int m0 = blockIdx.y * 128, n0 = blockIdx.x * 128;

    const uint8_t* Ap = A + (size_t)b * sAb + (size_t)m0 * lda;
    const uint8_t* Bp = B + (size_t)b * sBb + (size_t)n0 * ldb;

    auto issue = [&](int chunk) {
        const uint32_t st = sbase + (uint32_t)(chunk % NSTG) * STG_SIZE;
        const int k0 = chunk * 64;                 // 64 fp8 bytes per chunk
        #pragma unroll
        for (int i = 0; i < 4; i++) {              // 1024 x 16B: A (i<2) then B
            const int u = i * 256 + tid;
            const int r = (u >> 2) & 127;
            const int c = u & 3;
            const uint8_t* base = (i < 2) ? Ap : Bp;
            const int ld = (i < 2) ? lda : ldb;
            const uint8_t* src = base + (size_t)r * ld + k0 + c * 16;
            const uint32_t dst = st + (uint32_t)((i < 2 ? 0 : 10240) + r * PITCH + c * 16);
            CP_ASYNC16(dst, src);
        }
    };

    float acc[4][4][4];
    #pragma unroll
    for (int mf = 0; mf < 4; mf++)
        #pragma unroll
        for (int nf = 0; nf < 4; nf++)
            #pragma unroll
            for (int j = 0; j < 4; j++) acc[mf][nf][j] = 0.f;

    const int wm = (wid & 1) * 64;
    const int wn = (wid >> 1) * 32;
    const uint32_t pA = (uint32_t)((wm + (lane & 15)) * PITCH + (lane >> 4) * 16);
    const int grp = lane >> 3;
    const uint32_t pB = (uint32_t)((wn + (grp >> 1) * 8 + (lane & 7)) * PITCH + (grp & 1) * 16);

    auto compute = [&](uint32_t st) {
        const uint32_t aS = st, bS = st + 10240;
        #pragma unroll
        for (int ks = 0; ks < 2; ks++) {           // k-step = 32 bytes
            uint32_t AF[4][4], BF[4][2];
            #pragma unroll
            for (int mf = 0; mf < 4; mf++)
                ldsm_x4(AF[mf], aS + pA + (uint32_t)(mf * 16 * PITCH + ks * 32));
            #pragma unroll
            for (int nf2 = 0; nf2 < 2; nf2++) {
                uint32_t t4[4];
                ldsm_x4(t4, bS + pB + (uint32_t)(nf2 * 16 * PITCH + ks * 32));
                BF[2*nf2][0] = t4[0]; BF[2*nf2][1] = t4[1];
                BF[2*nf2+1][0] = t4[2]; BF[2*nf2+1][1] = t4[3];
            }
            #pragma unroll
            for (int mf = 0; mf < 4; mf++)
                #pragma unroll
                for (int nf = 0; nf < 4; nf++)
                    mma_fp8(acc[mf][nf], AF[mf], BF[nf]);
        }
    };

    issue(0); CP_COMMIT();
    issue(1); CP_COMMIT();
    issue(2); CP_COMMIT();

    for (int c = 0; c < nchunks; c++) {
        CP_WAIT2();
        __syncthreads();
        compute(sbase + (uint32_t)(c % NSTG) * STG_SIZE);
        if (c + 3 < nchunks) issue(c + 3);
        CP_COMMIT();
    }
    CP_WAIT0();

    bf16* Dp = D + (size_t)b * sDb;
    const int er = wm + (lane >> 2);
    const int ec = wn + 2 * (lane & 3);
    #pragma unroll
    for (int mf = 0; mf < 4; mf++)
        #pragma unroll
        for (int nf = 0; nf < 4; nf++) {
            size_t base0 = (size_t)(m0 + er + mf * 16) * ldd + (n0 + ec + nf * 8);
            *reinterpret_cast<__nv_bfloat162*>(Dp + base0) =
                __floats2bfloat162_rn(acc[mf][nf][0], acc[mf][nf][1]);
            *reinterpret_cast<__nv_bfloat162*>(Dp + base0 + (size_t)8 * ldd) =
                __floats2bfloat162_rn(acc[mf][nf][2], acc[mf][nf][3]);
        }
}

// ---------------- fused: fixed-reference softmax AWQ + gate ------------------
// One warp per c-row; context row staged in SMEM. WINDOW = 26 absorbs the fp8
// screen error (sigma ~2 per side): dropped-entry mass <= exp(-(26-2E)), total
// <= ~6e-5 for E<=5; a per-entry failure needs a ~7.8-sigma coincidence.
// __launch_bounds__(256,3) caps regs (~80) -> 3 CTAs/SM for latency hiding.
#define WINDOW 26.0f

__global__ __launch_bounds__(256, 3)
void softmax_awq_gate(const float* __restrict__ qry,
                      const float* __restrict__ ctx,
                      float* __restrict__ out) {
    __shared__ float          csh[8][DD];        // 24 KB
    __shared__ unsigned short idxs[8][512];      // 8 KB

    const int wid = threadIdx.x >> 5, lane = threadIdx.x & 31;
    const int c = blockIdx.x * 8 + wid;
    const int b = blockIdx.y;

    // stage context row into SMEM
    const float4* C4 = reinterpret_cast<const float4*>(ctx + ((size_t)b * LC + c) * DD);
    float4* csh4 = reinterpret_cast<float4*>(csh[wid]);
    #pragma unroll
    for (int j = 0; j < 6; j++) csh4[lane + 32 * j] = C4[lane + 32 * j];

    // scan approximate scores, warp max
    const __nv_bfloat162* S2 =
        reinterpret_cast<const __nv_bfloat162*>(g_S + ((size_t)b * LC + c) * LQ);
    float sv[16];
    float m = -3.0e38f;
    #pragma unroll
    for (int i = 0; i < 8; i++) {
        float2 v = __bfloat1622float2(S2[lane + 32 * i]);
        sv[2 * i]     = v.x;
        sv[2 * i + 1] = v.y;
        m = fmaxf(m, fmaxf(v.x, v.y));
    }
    #pragma unroll
    for (int off = 16; off; off >>= 1)
        m = fmaxf(m, __shfl_xor_sync(0xffffffffu, m, off));
    const float thr = m - WINDOW;

    // candidate index list (ballot + prefix popc; cnt uniform)
    int cnt = 0;
    #pragma unroll
    for (int k = 0; k < 16; k++) {
        const bool hit = sv[k] > thr;
        const unsigned mask = __ballot_sync(0xffffffffu, hit);
        if (hit) {
            const int pos = cnt + __popc(mask & ((1u << lane) - 1u));
            idxs[wid][pos] = (unsigned short)(64 * (k >> 1) + 2 * lane + (k & 1));
        }
        cnt += __popc(mask);
    }
    __syncwarp();

    const float* Qb = qry + (size_t)b * LQ * DD;
    float Z = 0.f;
    float4 acc[6];
    #pragma unroll
    for (int j = 0; j < 6; j++) acc[j] = make_float4(0.f, 0.f, 0.f, 0.f);

    for (int j0 = 0; j0 < cnt; j0++) {
        const float4* Q4 = reinterpret_cast<const float4*>(
            Qb + (size_t)idxs[wid][j0] * DD);

        float4 qv[6];
        #pragma unroll
        for (int t = 0; t < 6; t++) qv[t] = Q4[lane + 32 * t];

        float d = 0.f;
        #pragma unroll
        for (int t = 0; t < 6; t++) {
            const float4 cvv = csh4[lane + 32 * t];
            d += cvv.x * qv[t].x + cvv.y * qv[t].y +
                 cvv.z * qv[t].z + cvv.w * qv[t].w;
        }
        #pragma unroll
        for (int off = 16; off; off >>= 1)
            d += __shfl_xor_sync(0xffffffffu, d, off);

        const float w = __expf(d - m);
        Z += w;
        #pragma unroll
        for (int t = 0; t < 6; t++) {
            acc[t].x = fmaf(w, qv[t].x, acc[t].x);
            acc[t].y = fmaf(w, qv[t].y, acc[t].y);
            acc[t].z = fmaf(w, qv[t].z, acc[t].z);
            acc[t].w = fmaf(w, qv[t].w, acc[t].w);
        }
    }

    const float invZ = 1.0f / Z;
    float4* O4 = reinterpret_cast<float4*>(out + ((size_t)b * LC + c) * DD);
    #pragma unroll
    for (int j = 0; j < 6; j++) {
        const float4 cvv = csh4[lane + 32 * j];
        O4[lane + 32 * j] = make_float4(cvv.x * acc[j].x * invZ,
                                        cvv.y * acc[j].y * invZ,
                                        cvv.z * acc[j].z * invZ,
                                        cvv.w * acc[j].w * invZ);
    }
}

// ---------------- host launch ----------------
extern "C" void kernel_launch(void* const* d_in, const int* in_sizes, int n_in,
                              void* d_out, int out_size) {
    const float* a0 = (const float*)d_in[0];
    const float* a1 = (const float*)d_in[1];
    const float* ctx;
    const float* qry;
    if (in_sizes[0] == BB * LC * DD) { ctx = a0; qry = a1; }
    else                             { ctx = a1; qry = a0; }
    float* out = (float*)d_out;

    void *pC8, *pQ8, *pS;
    cudaGetSymbolAddress(&pC8, g_C8);
    cudaGetSymbolAddress(&pQ8, g_Q8);
    cudaGetSymbolAddress(&pS, g_S);

    cudaFuncSetAttribute(gemm_fp8,
                         cudaFuncAttributeMaxDynamicSharedMemorySize, SM_TOTAL);

    // 1) convert C and Q to e4m3 (screening precision)
    {
        int n4 = BB * LC * DD / 4;
        to_fp8_kernel<<<(n4 + 255) / 256, 256>>>(ctx, (uint32_t*)pC8, n4);
    }
    {
        int n4 = BB * LQ * DD / 4;
        to_fp8_kernel<<<(n4 + 255) / 256, 256>>>(qry, (uint32_t*)pQ8, n4);
    }
    // 2) FP8 screening GEMM: S_approx[c][q] = C . Q^T
    {
        dim3 grid(LQ / 128, LC / 128, BB);
        gemm_fp8<<<grid, 256, SM_TOTAL>>>(
            (const uint8_t*)pC8, DD, (long)LC * DD,
            (const uint8_t*)pQ8, DD, (long)LQ * DD,
            DD / 64,
            (bf16*)pS, LQ, (long)LC * LQ);
    }
    // 3) fused: candidates -> exact logits -> fixed-ref softmax AWQ -> gate
    {
        dim3 grid(LC / 8, BB);
        softmax_awq_gate<<<grid, 256>>>(qry, ctx, out);
    }
}

// round 17
// speedup vs baseline: 1.2595x; 1.2595x over previous
#include <cuda_runtime.h>
#include <cuda_bf16.h>
#include <stdint.h>

typedef __nv_bfloat16 bf16;

#define BB 8
#define LQ 512
#define LC 2048
#define DD 768

// ---------------- scratch (device globals; allocation-free) ----------------
__device__ __align__(128) bf16 g_Chi[BB * LC * DD];
__device__ __align__(128) bf16 g_Qhi[BB * LQ * DD];
__device__ __align__(128) bf16 g_S[BB * LC * LQ];   // approximate logits S_t[b][c][q]

// ---------------- helpers ----------------
__device__ __forceinline__ uint32_t smem_u32(const void* p) {
    uint32_t a;
    asm("{ .reg .u64 t; cvta.to.shared.u64 t, %1; cvt.u32.u64 %0, t; }" : "=r"(a) : "l"(p));
    return a;
}
#define CP_ASYNC16(dst, src) \
    asm volatile("cp.async.cg.shared.global [%0], [%1], 16;" :: "r"(dst), "l"(src))
#define CP_COMMIT() asm volatile("cp.async.commit_group;" ::: "memory")
#define CP_WAIT2()  asm volatile("cp.async.wait_group 2;" ::: "memory")
#define CP_WAIT0()  asm volatile("cp.async.wait_group 0;" ::: "memory")

__device__ __forceinline__ void ldsm_x4(uint32_t* r, uint32_t a) {
    asm volatile("ldmatrix.sync.aligned.m8n8.x4.shared.b16 {%0,%1,%2,%3}, [%4];"
                 : "=r"(r[0]), "=r"(r[1]), "=r"(r[2]), "=r"(r[3]) : "r"(a));
}
__device__ __forceinline__ void mma16816(float* d, const uint32_t* a, const uint32_t* b) {
    asm volatile(
        "mma.sync.aligned.m16n8k16.row.col.f32.bf16.bf16.f32 "
        "{%0,%1,%2,%3}, {%4,%5,%6,%7}, {%8,%9}, {%0,%1,%2,%3};"
        : "+f"(d[0]), "+f"(d[1]), "+f"(d[2]), "+f"(d[3])
        : "r"(a[0]), "r"(a[1]), "r"(a[2]), "r"(a[3]), "r"(b[0]), "r"(b[1]));
}

// ---------------- kernel: fp32 -> bf16 convert ----------------
__global__ __launch_bounds__(256)
void to_bf16_kernel(const float* __restrict__ x, bf16* __restrict__ hi, int n4) {
    int i = blockIdx.x * 256 + threadIdx.x;
    if (i >= n4) return;
    float4 v = reinterpret_cast<const float4*>(x)[i];
    __nv_bfloat162* h2p = reinterpret_cast<__nv_bfloat162*>(hi) + 2 * i;
    h2p[0] = __floats2bfloat162_rn(v.x, v.y);
    h2p[1] = __floats2bfloat162_rn(v.z, v.w);
}

// ---------------- 1-term bf16 HMMA screening GEMM (at legacy-pipe MAC cap) ---
#define PITCH    80
#define STG_SIZE 20480
#define NSTG     4
#define SM_TOTAL (NSTG * STG_SIZE)   // 81920 -> 2 CTAs/SM

__global__ __launch_bounds__(256, 2)
void gemm_hh(const bf16* __restrict__ A, int lda, long sAb,
             const bf16* __restrict__ B, int ldb, long sBb,
             int nchunks,
             bf16* __restrict__ D, int ldd, long sDb) {
    extern __shared__ char smem[];
    const uint32_t sbase = smem_u32(smem);
    const int tid = threadIdx.x, wid = tid >> 5, lane = tid & 31;
    const int b  = blockIdx.z;
    const int m0 = blockIdx.y * 128, n0 = blockIdx.x * 128;

    const bf16* Ap = A + (size_t)b * sAb + (size_t)m0 * lda;
    const bf16* Bp = B + (size_t)b * sBb + (size_t)n0 * ldb;

    auto issue = [&](int chunk) {
        const uint32_t st = sbase + (uint32_t)(chunk % NSTG) * STG_SIZE;
        const int k0 = chunk * 32;
        #pragma unroll
        for (int i = 0; i < 4; i++) {
            const int u = i * 256 + tid;
            const int r = (u >> 2) & 127;
            const int c = u & 3;
            const bf16* base = (i < 2) ? Ap : Bp;
            const int ld = (i < 2) ? lda : ldb;
            const bf16* src = base + (size_t)r * ld + k0 + c * 8;
            const uint32_t dst = st + (uint32_t)((i < 2 ? 0 : 10240) + r * PITCH + c * 16);
            CP_ASYNC16(dst, src);
        }
    };

    float acc[4][4][4];
    #pragma unroll
    for (int mf = 0; mf < 4; mf++)
        #pragma unroll
        for (int nf = 0; nf < 4; nf++)
            #pragma unroll
            for (int j = 0; j < 4; j++) acc[mf][nf][j] = 0.f;

    const int wm = (wid & 1) * 64;
    const int wn = (wid >> 1) * 32;
    const uint32_t pA = (uint32_t)((wm + (lane & 15)) * PITCH + (lane >> 4) * 16);
    const int grp = lane >> 3;
    const uint32_t pB = (uint32_t)((wn + (grp >> 1) * 8 + (lane & 7)) * PITCH + (grp & 1) * 16);

    auto compute = [&](uint32_t st) {
        const uint32_t aS = st, bS = st + 10240;
        #pragma unroll
        for (int ks = 0; ks < 2; ks++) {
            uint32_t AF[4][4], BF[4][2];
            #pragma unroll
            for (int mf = 0; mf < 4; mf++)
                ldsm_x4(AF[mf], aS + pA + (uint32_t)(mf * 16 * PITCH + ks * 32));
            #pragma unroll
            for (int nf2 = 0; nf2 < 2; nf2++) {
                uint32_t t4[4];
                ldsm_x4(t4, bS + pB + (uint32_t)(nf2 * 16 * PITCH + ks * 32));
                BF[2*nf2][0] = t4[0]; BF[2*nf2][1] = t4[1];
                BF[2*nf2+1][0] = t4[2]; BF[2*nf2+1][1] = t4[3];
            }
            #pragma unroll
            for (int mf = 0; mf < 4; mf++)
                #pragma unroll
                for (int nf = 0; nf < 4; nf++)
                    mma16816(acc[mf][nf], AF[mf], BF[nf]);
        }
    };

    issue(0); CP_COMMIT();
    issue(1); CP_COMMIT();
    issue(2); CP_COMMIT();

    for (int c = 0; c < nchunks; c++) {
        CP_WAIT2();
        __syncthreads();
        compute(sbase + (uint32_t)(c % NSTG) * STG_SIZE);
        if (c + 3 < nchunks) issue(c + 3);
        CP_COMMIT();
    }
    CP_WAIT0();

    bf16* Dp = D + (size_t)b * sDb;
    const int er = wm + (lane >> 2);
    const int ec = wn + 2 * (lane & 3);
    #pragma unroll
    for (int mf = 0; mf < 4; mf++)
        #pragma unroll
        for (int nf = 0; nf < 4; nf++) {
            size_t base0 = (size_t)(m0 + er + mf * 16) * ldd + (n0 + ec + nf * 8);
            *reinterpret_cast<__nv_bfloat162*>(Dp + base0) =
                __floats2bfloat162_rn(acc[mf][nf][0], acc[mf][nf][1]);
            *reinterpret_cast<__nv_bfloat162*>(Dp + base0 + (size_t)8 * ldd) =
                __floats2bfloat162_rn(acc[mf][nf][2], acc[mf][nf][3]);
        }
}

// ---------------- fused: fixed-reference softmax AWQ + gate ------------------
// R14 structure (bf16 screen, WINDOW=16, SMEM-staged context) + R15's verified
// 3-CTA/SM occupancy cap (regs ~80). Dropped mass <= 512*exp(-15.5) ~ 9e-5,
// unconditionally under the 1e-3 gate.
#define WINDOW 16.0f

__global__ __launch_bounds__(256, 3)
void softmax_awq_gate(const float* __restrict__ qry,
                      const float* __restrict__ ctx,
                      float* __restrict__ out) {
    __shared__ float          csh[8][DD];        // 24 KB
    __shared__ unsigned short idxs[8][512];      // 8 KB

    const int wid = threadIdx.x >> 5, lane = threadIdx.x & 31;
    const int c = blockIdx.x * 8 + wid;
    const int b = blockIdx.y;

    // stage context row into SMEM
    const float4* C4 = reinterpret_cast<const float4*>(ctx + ((size_t)b * LC + c) * DD);
    float4* csh4 = reinterpret_cast<float4*>(csh[wid]);
    #pragma unroll
    for (int j = 0; j < 6; j++) csh4[lane + 32 * j] = C4[lane + 32 * j];

    // scan approximate scores, warp max
    const __nv_bfloat162* S2 =
        reinterpret_cast<const __nv_bfloat162*>(g_S + ((size_t)b * LC + c) * LQ);
    float sv[16];
    float m = -3.0e38f;
    #pragma unroll
    for (int i = 0; i < 8; i++) {
        float2 v = __bfloat1622float2(S2[lane + 32 * i]);
        sv[2 * i]     = v.x;
        sv[2 * i + 1] = v.y;
        m = fmaxf(m, fmaxf(v.x, v.y));
    }
    #pragma unroll
    for (int off = 16; off; off >>= 1)
        m = fmaxf(m, __shfl_xor_sync(0xffffffffu, m, off));
    const float thr = m - WINDOW;

    // candidate index list (ballot + prefix popc; cnt uniform)
    int cnt = 0;
    #pragma unroll
    for (int k = 0; k < 16; k++) {
        const bool hit = sv[k] > thr;
        const unsigned mask = __ballot_sync(0xffffffffu, hit);
        if (hit) {
            const int pos = cnt + __popc(mask & ((1u << lane) - 1u));
            idxs[wid][pos] = (unsigned short)(64 * (k >> 1) + 2 * lane + (k & 1));
        }
        cnt += __popc(mask);
    }
    __syncwarp();

    const float* Qb = qry + (size_t)b * LQ * DD;
    float Z = 0.f;
    float4 acc[6];
    #pragma unroll
    for (int j = 0; j < 6; j++) acc[j] = make_float4(0.f, 0.f, 0.f, 0.f);

    for (int j0 = 0; j0 < cnt; j0++) {
        const float4* Q4 = reinterpret_cast<const float4*>(
            Qb + (size_t)idxs[wid][j0] * DD);

        float4 qv[6];
        #pragma unroll
        for (int t = 0; t < 6; t++) qv[t] = Q4[lane + 32 * t];

        float d = 0.f;
        #pragma unroll
        for (int t = 0; t < 6; t++) {
            const float4 cvv = csh4[lane + 32 * t];
            d += cvv.x * qv[t].x + cvv.y * qv[t].y +
                 cvv.z * qv[t].z + cvv.w * qv[t].w;
        }
        #pragma unroll
        for (int off = 16; off; off >>= 1)
            d += __shfl_xor_sync(0xffffffffu, d, off);

        const float w = __expf(d - m);
        Z += w;
        #pragma unroll
        for (int t = 0; t < 6; t++) {
            acc[t].x = fmaf(w, qv[t].x, acc[t].x);
            acc[t].y = fmaf(w, qv[t].y, acc[t].y);
            acc[t].z = fmaf(w, qv[t].z, acc[t].z);
            acc[t].w = fmaf(w, qv[t].w, acc[t].w);
        }
    }

    const float invZ = 1.0f / Z;
    float4* O4 = reinterpret_cast<float4*>(out + ((size_t)b * LC + c) * DD);
    #pragma unroll
    for (int j = 0; j < 6; j++) {
        const float4 cvv = csh4[lane + 32 * j];
        O4[lane + 32 * j] = make_float4(cvv.x * acc[j].x * invZ,
                                        cvv.y * acc[j].y * invZ,
                                        cvv.z * acc[j].z * invZ,
                                        cvv.w * acc[j].w * invZ);
    }
}

// ---------------- host launch ----------------
extern "C" void kernel_launch(void* const* d_in, const int* in_sizes, int n_in,
                              void* d_out, int out_size) {
    const float* a0 = (const float*)d_in[0];
    const float* a1 = (const float*)d_in[1];
    const float* ctx;
    const float* qry;
    if (in_sizes[0] == BB * LC * DD) { ctx = a0; qry = a1; }
    else                             { ctx = a1; qry = a0; }
    float* out = (float*)d_out;

    void *pChi, *pQhi, *pS;
    cudaGetSymbolAddress(&pChi, g_Chi);
    cudaGetSymbolAddress(&pQhi, g_Qhi);
    cudaGetSymbolAddress(&pS, g_S);

    cudaFuncSetAttribute(gemm_hh,
                         cudaFuncAttributeMaxDynamicSharedMemorySize, SM_TOTAL);

    // 1) convert C and Q to bf16 (screening precision)
    {
        int n4 = BB * LC * DD / 4;
        to_bf16_kernel<<<(n4 + 255) / 256, 256>>>(ctx, (bf16*)pChi, n4);
    }
    {
        int n4 = BB * LQ * DD / 4;
        to_bf16_kernel<<<(n4 + 255) / 256, 256>>>(qry, (bf16*)pQhi, n4);
    }
    // 2) screening GEMM: S_approx[c][q] = C . Q^T
    {
        dim3 grid(LQ / 128, LC / 128, BB);
        gemm_hh<<<grid, 256, SM_TOTAL>>>(
            (const bf16*)pChi, DD, (long)LC * DD,
            (const bf16*)pQhi, DD, (long)LQ * DD,
            DD / 32,
            (bf16*)pS, LQ, (long)LC * LQ);
    }
    // 3) fused: candidates -> exact logits -> fixed-ref softmax AWQ -> gate
    {
        dim3 grid(LC / 8, BB);
        softmax_awq_gate<<<grid, 256>>>(qry, ctx, out);
    }
}